// round 10
// baseline (speedup 1.0000x reference)
#include <cuda_runtime.h>

#define NN 128
#define TT 2048
#define DD 88
#define D4 22                 // float4 per row

__device__ unsigned int g_pack[NN * TT];   // per-row: fpfn | tp<<8 | mask<<16
__device__ float        g_acc[NN];
__device__ unsigned int g_done = 0;

// ---------------------------------------------------------------------------
// k1: one warp per (n,t) row. Lanes 0..21: one float4 from output + target.
// Lane 22: mask. Single REDUX.SUM reduces all three packed fields at once.
// Scratch stored with an L2 evict_last cache-hint policy so k2 finds it hot.
// ---------------------------------------------------------------------------
__global__ void __launch_bounds__(256) k1_rowstats(
    const float4* __restrict__ outp,
    const float4* __restrict__ tgtp,
    const int*    __restrict__ mask)
{
    const int n    = blockIdx.y;
    const int t    = blockIdx.x * 8 + threadIdx.y;
    const int lane = threadIdx.x;

    const int    row  = n * TT + t;
    const size_t base = (size_t)row * D4 + lane;

    unsigned int v = 0;
    if (lane < D4) {
        const float4 o = outp[base];
        const float4 g = tgtp[base];
        int tp = 0, fp = 0;
        #define ELEM(ov, gv) {                      \
            const bool p = ((ov) > 0.f);            \
            const bool q = ((gv) != 0.f);           \
            tp += (p && q) ? 1 : 0;                 \
            fp += (p != q) ? 1 : 0; }
        ELEM(o.x, g.x) ELEM(o.y, g.y) ELEM(o.z, g.z) ELEM(o.w, g.w)
        #undef ELEM
        v = (unsigned)fp | ((unsigned)tp << 8);
    } else if (lane == D4) {
        v = ((unsigned)mask[row]) << 16;
    }

    v = __reduce_add_sync(0xffffffffu, v);   // fpfn<=88 | tp<=88<<8 | mask<=1<<16

    if (lane == 0) {
        asm volatile(
            "{\n\t"
            ".reg .b64 pol;\n\t"
            "createpolicy.fractional.L2::evict_last.b64 pol, 1.0;\n\t"
            "st.global.L2::cache_hint.b32 [%0], %1, pol;\n\t"
            "}"
            :: "l"(&g_pack[row]), "r"(v) : "memory");
    }
}

// ---------------------------------------------------------------------------
// k2: one block of 1024 threads per sequence n. One uint2 (2 rows) per
// thread; REDUX block reduce for tp/Ti; 2 divides per thread; fused
// deterministic final reduction via last-block counter.
// ---------------------------------------------------------------------------
__global__ void __launch_bounds__(1024) k2_finish(float* __restrict__ out)
{
    const int n    = blockIdx.x;
    const int tid  = threadIdx.x;
    const int warp = tid >> 5;
    const int lane = tid & 31;

    __shared__ unsigned int s_i[32];
    __shared__ float        s_f[32];
    __shared__ int          s_last;

    const uint2 w = ((const uint2*)g_pack)[n * 1024 + tid];
    const unsigned fp0 =  w.x        & 0xffu;
    const unsigned tp0 = (w.x >> 8)  & 0xffu;
    const unsigned ti0 = (w.x >> 16) & 0x1u;
    const unsigned fp1 =  w.y        & 0xffu;
    const unsigned tp1 = (w.y >> 8)  & 0xffu;
    const unsigned ti1 = (w.y >> 16) & 0x1u;

    // pack tp (<=180224, 18 bits) | Ti<<18
    unsigned int pk = (tp0 + tp1) | ((ti0 + ti1) << 18);
    pk = __reduce_add_sync(0xffffffffu, pk);
    if (lane == 0) s_i[warp] = pk;
    __syncthreads();
    if (warp == 0) {
        unsigned int u = __reduce_add_sync(0xffffffffu, s_i[lane]);
        if (lane == 0) s_i[0] = u;
    }
    __syncthreads();
    const unsigned tot = s_i[0];
    const float tpf = (float)(tot & 0x3ffffu);
    const int   Ti  = (int)(tot >> 18);

    float acc = 0.f;
    if (2 * tid     < Ti) acc += __fdividef(tpf, tpf + (float)fp0);
    if (2 * tid + 1 < Ti) acc += __fdividef(tpf, tpf + (float)fp1);

    #pragma unroll
    for (int off = 16; off; off >>= 1)
        acc += __shfl_down_sync(0xffffffffu, acc, off);
    if (lane == 0) s_f[warp] = acc;
    __syncthreads();
    if (warp == 0) {
        float a = s_f[lane];
        #pragma unroll
        for (int off = 16; off; off >>= 1)
            a += __shfl_down_sync(0xffffffffu, a, off);
        if (lane == 0) g_acc[n] = a / (float)Ti;
    }

    // ---- fused deterministic final reduction ----
    if (tid == 0) {
        __threadfence();
        unsigned int old = atomicAdd(&g_done, 1u);
        s_last = (old == (unsigned)(gridDim.x - 1)) ? 1 : 0;
    }
    __syncthreads();
    if (s_last && warp == 0) {
        __threadfence();
        float v = g_acc[lane] + g_acc[lane + 32] + g_acc[lane + 64] + g_acc[lane + 96];
        #pragma unroll
        for (int off = 16; off; off >>= 1)
            v += __shfl_down_sync(0xffffffffu, v, off);
        if (lane == 0) {
            out[0]  = v;
            g_done = 0;          // reset for next graph replay
        }
    }
}

extern "C" void kernel_launch(void* const* d_in, const int* in_sizes, int n_in,
                              void* d_out, int out_size)
{
    const float4* outp = (const float4*)d_in[0];
    const float4* tgtp = (const float4*)d_in[1];
    const int*    mask = (const int*)  d_in[2];
    float*        out  = (float*)d_out;

    dim3 grid1(TT / 8, NN);     // 256 x 128 blocks
    dim3 blk1(32, 8);           // one warp per row
    k1_rowstats<<<grid1, blk1>>>(outp, tgtp, mask);
    k2_finish<<<NN, 1024>>>(out);
}

// round 13
// speedup vs baseline: 1.2921x; 1.2921x over previous
#include <cuda_runtime.h>

#define NN 128
#define TT 2048
#define DD 88
#define D4 22                  // float4 per row
#define NW (NN * TT / 2)       // 131072 warp-words, one per 2 rows (1024 per n)

__device__ unsigned int g_w[NW];      // f0 | f1<<8 | tp<<16 | ti<<26
__device__ float        g_acc[NN];
__device__ unsigned int g_done = 0;

// ---------------------------------------------------------------------------
// k1: one warp per 2 rows. Lanes 0..21 carry one float4 from each array for
// each of the 2 rows (4 front-batched LDG.128); lanes 22,23 read mask.
// Single packed word, single 5-SHFL reduce, single STG.32. No smem/sync.
// ---------------------------------------------------------------------------
__global__ void __launch_bounds__(256) k1_rowstats(
    const float4* __restrict__ outp,
    const float4* __restrict__ tgtp,
    const int*    __restrict__ mask)
{
    const int w    = blockIdx.x * 8 + (threadIdx.x >> 5);  // global warp id
    const int lane = threadIdx.x & 31;
    const int r0   = w * 2;                                // first row

    const size_t base = (size_t)r0 * D4 + lane;
    const bool   act  = (lane < D4);

    float4 o0, o1, g0, g1;
    if (act) {
        o0 = __ldcs(outp + base);
        o1 = __ldcs(outp + base + D4);
        g0 = __ldcs(tgtp + base);
        g1 = __ldcs(tgtp + base + D4);
    }
    unsigned int v = 0;
    if (lane == D4)     v = ((unsigned)mask[r0])     << 26;
    if (lane == D4 + 1) v = ((unsigned)mask[r0 + 1]) << 26;

    if (act) {
        int f0 = 0, f1 = 0, tp = 0;
        #define ELEM(ov, gv, fv) {                    \
            const bool p = ((ov) > 0.f);              \
            const bool q = ((gv) != 0.f);             \
            tp += (p && q) ? 1 : 0;                   \
            fv += (p != q) ? 1 : 0; }
        ELEM(o0.x, g0.x, f0) ELEM(o0.y, g0.y, f0) ELEM(o0.z, g0.z, f0) ELEM(o0.w, g0.w, f0)
        ELEM(o1.x, g1.x, f1) ELEM(o1.y, g1.y, f1) ELEM(o1.z, g1.z, f1) ELEM(o1.w, g1.w, f1)
        #undef ELEM
        v = (unsigned)f0 | ((unsigned)f1 << 8) | ((unsigned)tp << 16);
    }

    // one short reduce: field maxima f0=88, f1=88, tp=176, ti=2 -> no carry
    #pragma unroll
    for (int off = 16; off; off >>= 1)
        v += __shfl_down_sync(0xffffffffu, v, off);

    if (lane == 0) g_w[w] = v;
}

// ---------------------------------------------------------------------------
// k2: one block (1024 thr) per sequence n; thread j owns warp-word j
// (local rows 2j, 2j+1). Reduce tp/Ti over all 1024 words, 2 divides per
// thread, per-n acc, fused deterministic final reduction.
// ---------------------------------------------------------------------------
__global__ void __launch_bounds__(1024) k2_finish(float* __restrict__ out)
{
    const int n    = blockIdx.x;
    const int tid  = threadIdx.x;
    const int warp = tid >> 5;
    const int lane = tid & 31;

    __shared__ unsigned int s_i[32];
    __shared__ float        s_f[32];
    __shared__ int          s_last;

    const unsigned int w  = g_w[n * 1024 + tid];
    const float f0 = (float)( w        & 0xffu);
    const float f1 = (float)((w >> 8)  & 0xffu);
    const unsigned tp = (w >> 16) & 0x3ffu;
    const unsigned ti = (w >> 26);

    // tp total <= 180224 (18 bits) | Ti<<18
    unsigned int pk = tp | (ti << 18);
    #pragma unroll
    for (int off = 16; off; off >>= 1)
        pk += __shfl_down_sync(0xffffffffu, pk, off);
    if (lane == 0) s_i[warp] = pk;
    __syncthreads();
    if (warp == 0) {
        unsigned int u = s_i[lane];
        #pragma unroll
        for (int off = 16; off; off >>= 1)
            u += __shfl_down_sync(0xffffffffu, u, off);
        if (lane == 0) s_i[0] = u;
    }
    __syncthreads();
    const unsigned tot = s_i[0];
    const float tpf = (float)(tot & 0x3ffffu);
    const int   Ti  = (int)(tot >> 18);

    float acc = 0.f;
    if (2 * tid     < Ti) acc += __fdividef(tpf, tpf + f0);
    if (2 * tid + 1 < Ti) acc += __fdividef(tpf, tpf + f1);

    #pragma unroll
    for (int off = 16; off; off >>= 1)
        acc += __shfl_down_sync(0xffffffffu, acc, off);
    if (lane == 0) s_f[warp] = acc;
    __syncthreads();
    if (warp == 0) {
        float a = s_f[lane];
        #pragma unroll
        for (int off = 16; off; off >>= 1)
            a += __shfl_down_sync(0xffffffffu, a, off);
        if (lane == 0) g_acc[n] = a / (float)Ti;
    }

    // ---- fused deterministic final reduction ----
    if (tid == 0) {
        __threadfence();
        unsigned int old = atomicAdd(&g_done, 1u);
        s_last = (old == (unsigned)(gridDim.x - 1)) ? 1 : 0;
    }
    __syncthreads();
    if (s_last && warp == 0) {
        __threadfence();
        float v = g_acc[lane] + g_acc[lane + 32] + g_acc[lane + 64] + g_acc[lane + 96];
        #pragma unroll
        for (int off = 16; off; off >>= 1)
            v += __shfl_down_sync(0xffffffffu, v, off);
        if (lane == 0) {
            out[0]  = v;
            g_done = 0;       // reset for next graph replay
        }
    }
}

extern "C" void kernel_launch(void* const* d_in, const int* in_sizes, int n_in,
                              void* d_out, int out_size)
{
    const float4* outp = (const float4*)d_in[0];
    const float4* tgtp = (const float4*)d_in[1];
    const int*    mask = (const int*)  d_in[2];
    float*        out  = (float*)d_out;

    k1_rowstats<<<NW / 8, 256>>>(outp, tgtp, mask);   // 16384 blocks, 8 warps each
    k2_finish<<<NN, 1024>>>(out);
}